// round 16
// baseline (speedup 1.0000x reference)
#include <cuda_runtime.h>
#include <cuda_bf16.h>
#include <cstdint>

#define T_STEPS 1024
#define BATCH   1024
#define INDIM   128
#define HID     16
#define NROWS   (T_STEPS * BATCH)
#define STRIDE  (BATCH * 64)          // floats per timestep in g_proj

#define RECUR_BLOCKS 128
#define ROWS_PER_PBLK 256
#define PROJ_BLOCKS  (NROWS / ROWS_PER_PBLK)   // 4096
#define PASS_T       16                        // timesteps per pass
#define NPASS        (T_STEPS / PASS_T)        // 64
#define BLKS_PER_PASS (PROJ_BLOCKS / NPASS)    // 64

// Scratch: per-(t,b) input projections. TRANSPOSED row layout:
// g_proj[row*64 + nl*4 + gate], row = t*BATCH + b, nl = hidden unit 0..15,
// gate in {f,i,g,o}. Lane j of the recurrence reads its 4 gates as one
// float4 at offset 4*j. Padded by 4 timesteps for the depth-4 prefetch.
__device__ float g_proj[(size_t)(NROWS + 4 * BATCH) * 64];
// Pre-packed B (weight) mma fragments, split-paired:
// uint4[(nt*8+s)*32+ln] = {b0.x, b0.y, b1.x, b1.y} (split0, split1).
__device__ uint32_t g_bfrag[8192];
// Per-pass producer completion counters (memset to 0 each launch).
__device__ int g_cnt[NPASS];

__device__ __forceinline__ uint32_t pack_bf2(__nv_bfloat16 lo, __nv_bfloat16 hi) {
    return ((uint32_t)__bfloat16_as_ushort(hi) << 16) | __bfloat16_as_ushort(lo);
}
// packed = { lo16 = bf16(losrc), hi16 = bf16(hisrc) }
__device__ __forceinline__ uint32_t cvt_pair(float hisrc, float losrc) {
    uint32_t r;
    asm("cvt.rn.bf16x2.f32 %0, %1, %2;" : "=r"(r) : "f"(hisrc), "f"(losrc));
    return r;
}
__device__ __forceinline__ int ld_acq(const int* p) {
    int v;
    asm volatile("ld.acquire.gpu.global.b32 %0, [%1];" : "=r"(v) : "l"(p) : "memory");
    return v;
}
__device__ __forceinline__ void wait_pass(int p) {
    const int* a = &g_cnt[p];
    while (ld_acq(a) < BLKS_PER_PASS) __nanosleep(128);
}

// =============== Kernel 0: one-shot W -> B-fragment conversion =============
// word w: comp = w&3 (split = comp>>1, reg = comp&1), ln = (w>>2)&31,
// s = (w>>7)&7, nt = (w>>10)&7.
// B fragment (m16n8k16.row.col): b0={B[2t][g],B[2t+1][g]}, b1 = k+8; g=ln>>2,
// t=ln&3, B[k][n] = W[n][k].
__global__ void __launch_bounds__(128) prep_bfrag(
    const float* __restrict__ Wf, const float* __restrict__ Wi,
    const float* __restrict__ Wg, const float* __restrict__ Wo)
{
    int w = blockIdx.x * 128 + threadIdx.x;
    int comp = w & 3;
    int ln = (w >> 2) & 31;
    int s = (w >> 7) & 7;
    int nt = (w >> 10) & 7;
    int split = comp >> 1, reg = comp & 1;
    int n = nt * 8 + (ln >> 2);
    int k0 = s * 16 + (ln & 3) * 2 + reg * 8;
    const float* wr = ((n < 16) ? Wf : (n < 32) ? Wi : (n < 48) ? Wg : Wo)
                      + (n & 15) * 144 + k0;
    float v0 = wr[0], v1 = wr[1];
    __nv_bfloat16 h0 = __float2bfloat16_rn(v0);
    __nv_bfloat16 h1 = __float2bfloat16_rn(v1);
    uint32_t outw;
    if (split == 0) {
        outw = pack_bf2(h0, h1);
    } else {
        __nv_bfloat16 l0 = __float2bfloat16_rn(v0 - __bfloat162float(h0));
        __nv_bfloat16 l1 = __float2bfloat16_rn(v1 - __bfloat162float(h1));
        outw = pack_bf2(l0, l1);
    }
    g_bfrag[w] = outw;
}

// ---------------- fast activations ----------------
__device__ __forceinline__ float fsigmoid(float x) {
    return __fdividef(1.f, 1.f + __expf(-x));
}
__device__ __forceinline__ float ftanh(float x) {
    float e = __expf(-2.f * x);
    return __fdividef(1.f - e, 1.f + e);
}

// ================== fused kernel: role by blockIdx.x =======================
// blocks [0,128): recurrence (all resident in wave 1; consumers).
// blocks [128, 128+4096): mma.sync split-bf16 GEMM, 2 M-tiles per block.
#define SM_BIAS 0
#define SM_BF   256                       // B frags copied from g_bfrag (32KB)
#define SM_A    (256 + 32768)             // A planes: 2 x 128 rows x 256B = 64KB
#define SM_TOT  (SM_A + 65536)            // 98560 B

__global__ void __launch_bounds__(128) fused(
    const float* __restrict__ x,
    const float* __restrict__ Wf, const float* __restrict__ bf_,
    const float* __restrict__ thf,
    const float* __restrict__ Wi, const float* __restrict__ bi_,
    const float* __restrict__ thi,
    const float* __restrict__ Wg, const float* __restrict__ bg_,
    const float* __restrict__ thg,
    const float* __restrict__ Wo, const float* __restrict__ bo_,
    const float* __restrict__ tho,
    float* __restrict__ out)
{
    extern __shared__ char smem[];
    int tid = threadIdx.x, warp = tid >> 5, lane = tid & 31;

    if (blockIdx.x >= RECUR_BLOCKS) {
        // ===================== producer: MMA GEMM ==========================
        int pbid = blockIdx.x - RECUR_BLOCKS;
        uint32_t sbase = (uint32_t)__cvta_generic_to_shared(smem);

        // bias + theta -> smem (theta folded: arg of sin is proj + matvec)
        if (tid < 64) {
            const float* bp = (tid < 16) ? bf_ : (tid < 32) ? bi_
                            : (tid < 48) ? bg_ : bo_;
            const float* tp = (tid < 16) ? thf : (tid < 32) ? thi
                            : (tid < 48) ? thg : tho;
            ((float*)(smem + SM_BIAS))[tid] = bp[tid & 15] + tp[tid & 15];
        }
        // B fragments: coalesced copy from g_bfrag (L2-resident 32KB)
#pragma unroll
        for (int i = 0; i < 16; i++)
            ((uint4*)(smem + SM_BF))[tid + 128 * i] =
                ((const uint4*)g_bfrag)[tid + 128 * i];

        int a_row = warp * 32 + (lane & 15);
        int a_hi8 = lane >> 4;

#pragma unroll 1
        for (int tile = 0; tile < 2; tile++) {
            if (tile) __syncthreads();   // protect A smem from prev mainloop

            // A: convert rows to bf16 hi/lo planes, coalesced STS.64
            size_t rowbase = (size_t)pbid * ROWS_PER_PBLK + tile * 128
                             + warp * 32;
            {
#pragma unroll 4
                for (int i = 0; i < 32; i++) {
                    float4 v = ((const float4*)x)[(rowbase + i) * 32 + lane];
                    int R = warp * 32 + i;
                    uint32_t addr = (uint32_t)(SM_A + R * 256 +
                        ((((lane >> 1) ^ (R & 7)) << 4) + (lane & 1) * 8));
                    uint32_t hi01 = cvt_pair(v.y, v.x);
                    uint32_t hi23 = cvt_pair(v.w, v.z);
                    float h0 = __uint_as_float(hi01 << 16);
                    float h1 = __uint_as_float(hi01 & 0xffff0000u);
                    float h2 = __uint_as_float(hi23 << 16);
                    float h3 = __uint_as_float(hi23 & 0xffff0000u);
                    uint32_t lo01 = cvt_pair(v.y - h1, v.x - h0);
                    uint32_t lo23 = cvt_pair(v.w - h3, v.z - h2);
                    *(uint2*)(smem + addr) = make_uint2(hi01, hi23);
                    *(uint2*)(smem + addr + 32768) = make_uint2(lo01, lo23);
                }
            }
            __syncthreads();

            float acc[2][8][4];
#pragma unroll
            for (int mt = 0; mt < 2; mt++)
#pragma unroll
                for (int nt = 0; nt < 8; nt++)
#pragma unroll
                    for (int r = 0; r < 4; r++) acc[mt][nt][r] = 0.f;

#pragma unroll 1
            for (int s = 0; s < 8; s++) {
                uint32_t af[2][2][4];
#pragma unroll
                for (int split = 0; split < 2; split++) {
#pragma unroll
                    for (int mt = 0; mt < 2; mt++) {
                        int R = a_row + mt * 16;
                        uint32_t addr = sbase + SM_A + split * 32768 + R * 256 +
                                        (((s * 2 + a_hi8) ^ (R & 7)) << 4);
                        asm volatile(
                            "ldmatrix.sync.aligned.m8n8.x4.shared.b16 "
                            "{%0,%1,%2,%3}, [%4];"
                            : "=r"(af[split][mt][0]), "=r"(af[split][mt][1]),
                              "=r"(af[split][mt][2]), "=r"(af[split][mt][3])
                            : "r"(addr));
                    }
                }
#pragma unroll
                for (int nt = 0; nt < 8; nt++) {
                    uint4 bq = *(const uint4*)(smem + SM_BF +
                        ((((nt * 8 + s) * 32) + lane) << 4));
#pragma unroll
                    for (int mt = 0; mt < 2; mt++) {
#define MMA(A, BX, BY)                                                       \
    asm volatile(                                                            \
        "mma.sync.aligned.m16n8k16.row.col.f32.bf16.bf16.f32 "               \
        "{%0,%1,%2,%3}, {%4,%5,%6,%7}, {%8,%9}, {%0,%1,%2,%3};"              \
        : "+f"(acc[mt][nt][0]), "+f"(acc[mt][nt][1]),                        \
          "+f"(acc[mt][nt][2]), "+f"(acc[mt][nt][3])                         \
        : "r"((A)[0]), "r"((A)[1]), "r"((A)[2]), "r"((A)[3]),                \
          "r"(BX), "r"(BY))
                        MMA(af[0][mt], bq.x, bq.y);   // xh*wh
                        MMA(af[0][mt], bq.z, bq.w);   // xh*wl
                        MMA(af[1][mt], bq.x, bq.y);   // xl*wh
#undef MMA
                    }
                }
            }

            // epilogue: + (bias+theta), transposed scatter stores
            int g = lane >> 2, t = lane & 3;
#pragma unroll
            for (int mt = 0; mt < 2; mt++) {
#pragma unroll
                for (int nt = 0; nt < 8; nt++) {
                    int n0 = nt * 8 + t * 2;
                    float2 bb = *(const float2*)(smem + SM_BIAS + n0 * 4);
                    int o0 = (n0 & 15) * 4 + (n0 >> 4);
                    int o1 = ((n0 + 1) & 15) * 4 + ((n0 + 1) >> 4);
                    size_t r0 = rowbase + mt * 16 + g;
                    float* p0 = g_proj + r0 * 64;
                    float* p1 = g_proj + (r0 + 8) * 64;
                    p0[o0] = acc[mt][nt][0] + bb.x;
                    p0[o1] = acc[mt][nt][1] + bb.y;
                    p1[o0] = acc[mt][nt][2] + bb.x;
                    p1[o1] = acc[mt][nt][3] + bb.y;
                }
            }
        }

        // release: all stores visible, then count this block into its pass
        __threadfence();
        __syncthreads();
        if (tid == 0) atomicAdd(&g_cnt[pbid >> 6], 1);
        return;
    }

    // ==================== consumer: recurrence =============================
    // Warp w handles batches 2w (lanes 0-15) and 2w+1 (lanes 16-31).
    // Lane owns hidden unit j = lane&15 with ALL FOUR gates.
    // h-exchange via per-warp smem (double-buffered), not shuffles.
    int w = blockIdx.x * 4 + warp;       // 0..511
    int l = tid & 31;
    int j = l & 15;
    int b = 2 * w + (l >> 4);            // this lane's batch element
    int seg = l & 16;
    const unsigned FULL = 0xffffffffu;

    float* hsh = (float*)smem + warp * 64;   // 2 buffers x 32 floats

    // Recurrent weights for all 4 gates (theta folded into GEMM bias).
    float wr0[16], wr1[16], wr2[16], wr3[16];
#pragma unroll
    for (int k = 0; k < 16; k++) {
        wr0[k] = Wf[j * 144 + 128 + k];
        wr1[k] = Wi[j * 144 + 128 + k];
        wr2[k] = Wg[j * 144 + 128 + k];
        wr3[k] = Wo[j * 144 + 128 + k];
    }

    float h = 0.f, c = 0.f;
    const float* pp = g_proj + (size_t)b * 64 + 4 * j;   // transposed rows
    float* op = out + (b << 4) + j;      // warp-contiguous: 2w*16 + l

    // Wait for pass 0 before preloading steps 0..3.
    wait_pass(0);
    float4 cur[4];
#pragma unroll
    for (int u = 0; u < 4; u++)
        cur[u] = *(const float4*)(pp + (size_t)u * STRIDE);

    for (int g = 0; g < T_STEPS / 4; g++) {
        // Next prefetch group belongs to pass (g+1)>>2; wait at pass entry.
        if (((g + 1) & 3) == 0 && ((g + 1) >> 2) < NPASS)
            wait_pass((g + 1) >> 2);

        float4 nxt[4];
#pragma unroll
        for (int u = 0; u < 4; u++)
            nxt[u] = *(const float4*)(pp + (size_t)(4 + u) * STRIDE);

#pragma unroll
        for (int u = 0; u < 4; u++) {
            // ---- h-exchange: STS.32 + 4x broadcast LDS.128 ----
            float* hb = hsh + (u & 1) * 32;
            hb[l] = h;
            __syncwarp();
            float4 hv0 = *(const float4*)(hb + seg + 0);
            float4 hv1 = *(const float4*)(hb + seg + 4);
            float4 hv2 = *(const float4*)(hb + seg + 8);
            float4 hv3 = *(const float4*)(hb + seg + 12);
            float hk[16] = {hv0.x, hv0.y, hv0.z, hv0.w,
                            hv1.x, hv1.y, hv1.z, hv1.w,
                            hv2.x, hv2.y, hv2.z, hv2.w,
                            hv3.x, hv3.y, hv3.z, hv3.w};

            // ---- matvec: 64 register FMAs, 2 partials per gate ----
            float p0a = 0.f, p0b = 0.f, p1a = 0.f, p1b = 0.f;
            float p2a = 0.f, p2b = 0.f, p3a = 0.f, p3b = 0.f;
#pragma unroll
            for (int k = 0; k < 16; k += 2) {
                p0a = fmaf(hk[k], wr0[k], p0a);
                p0b = fmaf(hk[k + 1], wr0[k + 1], p0b);
                p1a = fmaf(hk[k], wr1[k], p1a);
                p1b = fmaf(hk[k + 1], wr1[k + 1], p1b);
                p2a = fmaf(hk[k], wr2[k], p2a);
                p2b = fmaf(hk[k + 1], wr2[k + 1], p2b);
                p3a = fmaf(hk[k], wr3[k], p3a);
                p3b = fmaf(hk[k + 1], wr3[k + 1], p3b);
            }
            float a0 = cur[u].x + (p0a + p0b);
            float a1 = cur[u].y + (p1a + p1b);
            float a2 = cur[u].z + (p2a + p2b);
            float a3 = cur[u].w + (p3a + p3b);

            // ---- qgate: sin + 16-lane inclusive scan (4 gates) ----
            float s0 = __sinf(a0), s1 = __sinf(a1);
            float s2 = __sinf(a2), s3 = __sinf(a3);
            float c0 = s0, c1 = s1, c2 = s2, c3 = s3;
#pragma unroll
            for (int off = 1; off < 16; off <<= 1) {
                float u0 = __shfl_up_sync(FULL, c0, off, 16);
                float u1 = __shfl_up_sync(FULL, c1, off, 16);
                float u2 = __shfl_up_sync(FULL, c2, off, 16);
                float u3 = __shfl_up_sync(FULL, c3, off, 16);
                c0 += (j >= off) ? u0 : 0.f;
                c1 += (j >= off) ? u1 : 0.f;
                c2 += (j >= off) ? u2 : 0.f;
                c3 += (j >= off) ? u3 : 0.f;
            }
            float t0 = __shfl_sync(FULL, c0, seg + 15);
            float t1 = __shfl_sync(FULL, c1, seg + 15);
            float t2 = __shfl_sync(FULL, c2, seg + 15);
            float t3 = __shfl_sync(FULL, c3, seg + 15);
            float q0 = (j == 0) ? (s0 + t0) : c0;
            float q1 = (j == 0) ? (s1 + t1) : c1;
            float q2 = (j == 0) ? (s2 + t2) : c2;
            float q3 = (j == 0) ? (s3 + t3) : c3;

            // ---- activations + state update (all gates local) ----
            float f_ = fsigmoid(q0);
            float i_ = fsigmoid(q1);
            float g_ = ftanh(q2);
            float o_ = fsigmoid(q3);
            c = f_ * c + i_ * g_;
            h = o_ * ftanh(c);

            *op = h;                     // fully coalesced, all lanes
            op += BATCH * HID;
        }

#pragma unroll
        for (int u = 0; u < 4; u++) cur[u] = nxt[u];
        pp += (size_t)4 * STRIDE;
    }

    size_t base = (size_t)T_STEPS * BATCH * HID;
    out[base + (b << 4) + j] = h;
    out[base + BATCH * HID + (b << 4) + j] = c;
}

// ---------------- launch ----------------
extern "C" void kernel_launch(void* const* d_in, const int* in_sizes, int n_in,
                              void* d_out, int out_size) {
    const float* x   = (const float*)d_in[0];
    const float* Wf  = (const float*)d_in[1];
    const float* bf_ = (const float*)d_in[2];
    const float* thf = (const float*)d_in[3];
    const float* Wi  = (const float*)d_in[4];
    const float* bi_ = (const float*)d_in[5];
    const float* thi = (const float*)d_in[6];
    const float* Wg  = (const float*)d_in[7];
    const float* bg_ = (const float*)d_in[8];
    const float* thg = (const float*)d_in[9];
    const float* Wo  = (const float*)d_in[10];
    const float* bo_ = (const float*)d_in[11];
    const float* tho = (const float*)d_in[12];
    float* out = (float*)d_out;

    cudaFuncSetAttribute(fused,
                         cudaFuncAttributeMaxDynamicSharedMemorySize, SM_TOT);

    // Reset pass counters (graph-capturable async memset; no allocation).
    void* cnt_addr = nullptr;
    cudaGetSymbolAddress(&cnt_addr, g_cnt);
    cudaMemsetAsync(cnt_addr, 0, sizeof(int) * NPASS);

    prep_bfrag<<<64, 128>>>(Wf, Wi, Wg, Wo);
    fused<<<RECUR_BLOCKS + PROJ_BLOCKS, 128, SM_TOT>>>(
        x, Wf, bf_, thf, Wi, bi_, thi, Wg, bg_, thg, Wo, bo_, tho, out);
}